// round 9
// baseline (speedup 1.0000x reference)
#include <cuda_runtime.h>
#include <cuda_bf16.h>
#include <cstdint>

// Problem dims (fixed): B=8, N=2048, C=1024, D=16
#define BSZ 8
#define SEQ 2048
#define DM  1024
#define DS  16
#define TOT (BSZ * SEQ * DM)   // 16,777,216

#define NC    32               // scan chunks
#define CHUNK (SEQ / NC)       // 64 steps per chunk

#define LOG2E 1.4426950408889634f

// Scratch (allocation-free rule: static __device__ globals)
__device__ float          g_xf[(size_t)TOT];        // conv output fp32 (scan input)
__device__ float          g_dt[(size_t)TOT];        // dt after sigmoid scaling
__device__ __nv_bfloat16  g_xh[(size_t)TOT];        // hi(xf)
__device__ __nv_bfloat16  g_xl[(size_t)TOT];        // lo(xf)
__device__ __nv_bfloat16  g_wh[(size_t)DM * DM];    // hi(dt_w)
__device__ __nv_bfloat16  g_wl[(size_t)DM * DM];    // lo(dt_w)
// chunked-scan state, layout [b][ch][d][c]  (c fastest -> coalesced)
__device__ float g_P    [(size_t)BSZ * NC * DS * DM];  // chunk decay products
__device__ float g_Sloc [(size_t)BSZ * NC * DS * DM];  // chunk-local end states
__device__ float g_sinit[(size_t)BSZ * NC * DS * DM];  // per-chunk initial states

__device__ __forceinline__ float ex2f(float x) {
    float y; asm("ex2.approx.f32 %0, %1;" : "=f"(y) : "f"(x)); return y;
}
__device__ __forceinline__ float rcpf(float x) {
    float y; asm("rcp.approx.f32 %0, %1;" : "=f"(y) : "f"(x)); return y;
}

// 2^x on x in [-0.75, 0] via degree-6 Taylor (FMA pipe; max rel err ~1e-8
// on the actual domain [-0.46, 0]). Offloads MUFU pressure for half the states.
__device__ __forceinline__ float ex2poly(float x) {
    float p = fmaf(1.5403530e-4f, x, 1.3333558e-3f);
    p = fmaf(p, x, 9.6181291e-3f);
    p = fmaf(p, x, 5.5504109e-2f);
    p = fmaf(p, x, 2.4022651e-1f);
    p = fmaf(p, x, 6.9314718e-1f);
    p = fmaf(p, x, 1.0f);
    return p;
}

__device__ __forceinline__ void split_bf16(float v, __nv_bfloat16& h, __nv_bfloat16& l) {
    h = __float2bfloat16(v);
    l = __float2bfloat16(v - __bfloat162float(h));
}
__device__ __forceinline__ void cp16(void* s, const void* g) {
    uint32_t sa = (uint32_t)__cvta_generic_to_shared(s);
    asm volatile("cp.async.cg.shared.global [%0], [%1], 16;" :: "r"(sa), "l"(g));
}

// ---------------------------------------------------------------------------
// Kernel 1: depthwise conv k=3 pad=1 along sequence. float4-vectorized.
// ---------------------------------------------------------------------------
__global__ void conv_kernel(const float4* __restrict__ x4,
                            const float4* __restrict__ cw4,
                            const float4* __restrict__ cb4)
{
    int i4 = blockIdx.x * blockDim.x + threadIdx.x;      // 0 .. TOT/4-1
    if (i4 >= TOT / 4) return;
    int c4 = i4 & (DM / 4 - 1);
    int n  = (i4 >> 8) & (SEQ - 1);

    float4 wa = cw4[c4 * 3 + 0];
    float4 wb = cw4[c4 * 3 + 1];
    float4 wc = cw4[c4 * 3 + 2];
    float4 bb = cb4[c4];

    const float4 z = make_float4(0.f, 0.f, 0.f, 0.f);
    float4 xm = (n > 0)       ? x4[i4 - DM / 4] : z;
    float4 xc = x4[i4];
    float4 xp = (n < SEQ - 1) ? x4[i4 + DM / 4] : z;

    float4 y;
    y.x = fmaf(wa.x, xm.x, fmaf(wa.y, xc.x, fmaf(wa.z, xp.x, bb.x)));
    y.y = fmaf(wa.w, xm.y, fmaf(wb.x, xc.y, fmaf(wb.y, xp.y, bb.y)));
    y.z = fmaf(wb.z, xm.z, fmaf(wb.w, xc.z, fmaf(wc.x, xp.z, bb.z)));
    y.w = fmaf(wc.y, xm.w, fmaf(wc.z, xc.w, fmaf(wc.w, xp.w, bb.w)));

    ((float4*)g_xf)[i4] = y;

    __nv_bfloat16 h0, h1, h2, h3, l0, l1, l2, l3;
    split_bf16(y.x, h0, l0); split_bf16(y.y, h1, l1);
    split_bf16(y.z, h2, l2); split_bf16(y.w, h3, l3);
    __nv_bfloat162 hh01 = {h0, h1}, hh23 = {h2, h3};
    __nv_bfloat162 ll01 = {l0, l1}, ll23 = {l2, l3};
    uint2 hp, lp;
    hp.x = *(uint32_t*)&hh01; hp.y = *(uint32_t*)&hh23;
    lp.x = *(uint32_t*)&ll01; lp.y = *(uint32_t*)&ll23;
    *(uint2*)&g_xh[(size_t)i4 * 4] = hp;
    *(uint2*)&g_xl[(size_t)i4 * 4] = lp;
}

// ---------------------------------------------------------------------------
// Kernel 1b: split dt_w into bf16 hi/lo
// ---------------------------------------------------------------------------
__global__ void wsplit_kernel(const float4* __restrict__ w4)
{
    int i4 = blockIdx.x * blockDim.x + threadIdx.x;
    if (i4 >= DM * DM / 4) return;
    float4 v = w4[i4];
    __nv_bfloat16 h0, h1, h2, h3, l0, l1, l2, l3;
    split_bf16(v.x, h0, l0); split_bf16(v.y, h1, l1);
    split_bf16(v.z, h2, l2); split_bf16(v.w, h3, l3);
    __nv_bfloat162 hh01 = {h0, h1}, hh23 = {h2, h3};
    __nv_bfloat162 ll01 = {l0, l1}, ll23 = {l2, l3};
    uint2 hp, lp;
    hp.x = *(uint32_t*)&hh01; hp.y = *(uint32_t*)&hh23;
    lp.x = *(uint32_t*)&ll01; lp.y = *(uint32_t*)&ll23;
    *(uint2*)&g_wh[(size_t)i4 * 4] = hp;
    *(uint2*)&g_wl[(size_t)i4 * 4] = lp;
}

// ---------------------------------------------------------------------------
// Kernel 2: dt GEMM on tensor cores, bf16 3-pass hi/lo split, cp.async
// double-buffered. CTA 128x128x32, 8 warps x (32x64) via m16n8k16.
// ---------------------------------------------------------------------------
#define TBK 32
#define SPAD 40
#define PER_ARR (128 * SPAD)
#define PER_STAGE (4 * PER_ARR)
#define GEMM_SMEM (2 * PER_STAGE * 2)

__device__ __forceinline__ void mma_bf16(float* c, const uint32_t* a, const uint32_t* b) {
    asm volatile(
        "mma.sync.aligned.m16n8k16.row.col.f32.bf16.bf16.f32 "
        "{%0,%1,%2,%3},{%4,%5,%6,%7},{%8,%9},{%0,%1,%2,%3};"
        : "+f"(c[0]), "+f"(c[1]), "+f"(c[2]), "+f"(c[3])
        : "r"(a[0]), "r"(a[1]), "r"(a[2]), "r"(a[3]), "r"(b[0]), "r"(b[1]));
}

__global__ __launch_bounds__(256)
void gemm_dt_kernel(const float* __restrict__ bias)
{
    extern __shared__ __nv_bfloat16 sm[];

    const int tid  = threadIdx.x;
    const int lane = tid & 31;
    const int warp = tid >> 5;
    const int wm   = warp >> 1;
    const int wn   = warp & 1;
    const int qr   = lane >> 2;
    const int qc   = lane & 3;
    const int bm   = blockIdx.y * 128;
    const int bn   = blockIdx.x * 128;

    float acc[2][8][4];
#pragma unroll
    for (int mt = 0; mt < 2; ++mt)
#pragma unroll
        for (int nt = 0; nt < 8; ++nt)
#pragma unroll
            for (int r = 0; r < 4; ++r) acc[mt][nt][r] = 0.0f;

    auto load_stage = [&](int st, int k0) {
        __nv_bfloat16* base = sm + st * PER_STAGE;
#pragma unroll
        for (int i = 0; i < 2; ++i) {
            int f   = tid + i * 256;
            int row = f >> 2;
            int k8  = (f & 3) << 3;
            size_t ga = (size_t)(bm + row) * DM + k0 + k8;
            size_t gb = (size_t)(bn + row) * DM + k0 + k8;
            int so = row * SPAD + k8;
            cp16(base + 0 * PER_ARR + so, &g_xh[ga]);
            cp16(base + 1 * PER_ARR + so, &g_xl[ga]);
            cp16(base + 2 * PER_ARR + so, &g_wh[gb]);
            cp16(base + 3 * PER_ARR + so, &g_wl[gb]);
        }
        asm volatile("cp.async.commit_group;");
    };

    const int KT = DM / TBK;   // 32
    load_stage(0, 0);

    for (int kt = 0; kt < KT; ++kt) {
        asm volatile("cp.async.wait_group 0;");
        __syncthreads();
        if (kt + 1 < KT) load_stage((kt + 1) & 1, (kt + 1) * TBK);

        const __nv_bfloat16* Ah = sm + (kt & 1) * PER_STAGE + 0 * PER_ARR;
        const __nv_bfloat16* Al = Ah + PER_ARR;
        const __nv_bfloat16* Bh = Al + PER_ARR;
        const __nv_bfloat16* Bl = Bh + PER_ARR;

#pragma unroll
        for (int kst = 0; kst < TBK; kst += 16) {
            uint32_t ah[2][4], al[2][4];
#pragma unroll
            for (int mt = 0; mt < 2; ++mt) {
                int r0 = wm * 32 + mt * 16 + qr;
                int c0 = kst + qc * 2;
                ah[mt][0] = *(const uint32_t*)&Ah[(r0    ) * SPAD + c0    ];
                ah[mt][1] = *(const uint32_t*)&Ah[(r0 + 8) * SPAD + c0    ];
                ah[mt][2] = *(const uint32_t*)&Ah[(r0    ) * SPAD + c0 + 8];
                ah[mt][3] = *(const uint32_t*)&Ah[(r0 + 8) * SPAD + c0 + 8];
                al[mt][0] = *(const uint32_t*)&Al[(r0    ) * SPAD + c0    ];
                al[mt][1] = *(const uint32_t*)&Al[(r0 + 8) * SPAD + c0    ];
                al[mt][2] = *(const uint32_t*)&Al[(r0    ) * SPAD + c0 + 8];
                al[mt][3] = *(const uint32_t*)&Al[(r0 + 8) * SPAD + c0 + 8];
            }
            uint32_t bh[8][2], bl[8][2];
#pragma unroll
            for (int nt = 0; nt < 8; ++nt) {
                int nr = wn * 64 + nt * 8 + qr;
                int c0 = kst + qc * 2;
                bh[nt][0] = *(const uint32_t*)&Bh[nr * SPAD + c0    ];
                bh[nt][1] = *(const uint32_t*)&Bh[nr * SPAD + c0 + 8];
                bl[nt][0] = *(const uint32_t*)&Bl[nr * SPAD + c0    ];
                bl[nt][1] = *(const uint32_t*)&Bl[nr * SPAD + c0 + 8];
            }
#pragma unroll
            for (int mt = 0; mt < 2; ++mt)
#pragma unroll
                for (int nt = 0; nt < 8; ++nt) {
                    mma_bf16(acc[mt][nt], ah[mt], bh[nt]);
                    mma_bf16(acc[mt][nt], ah[mt], bl[nt]);
                    mma_bf16(acc[mt][nt], al[mt], bh[nt]);
                }
        }
        __syncthreads();
    }

#pragma unroll
    for (int mt = 0; mt < 2; ++mt) {
#pragma unroll
        for (int nt = 0; nt < 8; ++nt) {
            int row = bm + wm * 32 + mt * 16 + qr;
            int col = bn + wn * 64 + nt * 8 + qc * 2;
            float2 bb = *(const float2*)&bias[col];
#pragma unroll
            for (int half = 0; half < 2; ++half) {
                int r = row + half * 8;
                float r0 = acc[mt][nt][half * 2 + 0] + bb.x;
                float r1 = acc[mt][nt][half * 2 + 1] + bb.y;
                float s0 = rcpf(1.0f + ex2f(-r0 * LOG2E));
                float s1 = rcpf(1.0f + ex2f(-r1 * LOG2E));
                float2 v;
                v.x = fmaf(s0, 0.099f, 0.001f);
                v.y = fmaf(s1, 0.099f, 0.001f);
                *(float2*)&g_dt[(size_t)r * DM + col] = v;
            }
        }
    }
}

// ---------------------------------------------------------------------------
// Kernel 3a: chunk-local reduction ONLY. One thread per (b,c,chunk).
// Hybrid exp: states 0-7 on MUFU (ex2f), states 8-15 on FMA pipe (ex2poly).
// ---------------------------------------------------------------------------
__global__ __launch_bounds__(256)
void scan_pass1(const float* __restrict__ a_log,
                const float* __restrict__ Bm)
{
    int bb = blockIdx.z;
    int ch = blockIdx.y;
    int c  = blockIdx.x * 256 + threadIdx.x;

    float A2[DS], Bv[DS], s[DS];
#pragma unroll
    for (int d = 0; d < DS; ++d) {
        float z  = a_log[c * DS + d];
        float sp = fmaxf(z, 0.0f) + log1pf(__expf(-fabsf(z)));  // softplus
        A2[d] = -sp * LOG2E;
        Bv[d] = Bm[c * DS + d];
        s[d]  = 0.0f;
    }

    size_t base = ((size_t)bb * SEQ + (size_t)ch * CHUNK) * DM + c;
    const float* pdt = g_dt + base;
    const float* pxf = g_xf + base;

    float cum = 0.0f;
    float ndt = __ldcs(pdt), nxf = __ldcs(pxf);
    for (int t = 0; t < CHUNK; ++t) {
        float dt = ndt, xf = nxf;
        if (t + 1 < CHUNK) {
            ndt = __ldcs(pdt + (size_t)(t + 1) * DM);
            nxf = __ldcs(pxf + (size_t)(t + 1) * DM);
        }
        cum += dt;
        float u = dt * xf;
#pragma unroll
        for (int d = 0; d < DS; ++d) {
            float x = dt * A2[d];
            float e = (d < DS / 2) ? ex2f(x) : ex2poly(x);
            s[d] = fmaf(e, s[d], u * Bv[d]);
        }
    }

    size_t sb = (((size_t)bb * NC + ch) * DS) * DM + c;
#pragma unroll
    for (int d = 0; d < DS; ++d) {
        g_Sloc[sb + (size_t)d * DM] = s[d];
        g_P   [sb + (size_t)d * DM] = ex2f(A2[d] * cum);   // large-neg arg: MUFU
    }
}

// ---------------------------------------------------------------------------
// Kernel 3b: sequential combine across chunks (tiny). One thread per (b,c).
// ---------------------------------------------------------------------------
__global__ __launch_bounds__(256)
void scan_pass2()
{
    int t  = blockIdx.x * blockDim.x + threadIdx.x;   // 0..8191
    int bb = t >> 10;
    int c  = t & (DM - 1);

    float s[DS];
#pragma unroll
    for (int d = 0; d < DS; ++d) s[d] = 0.0f;

    for (int ch = 0; ch < NC; ++ch) {
        size_t sb = (((size_t)bb * NC + ch) * DS) * DM + c;
#pragma unroll
        for (int d = 0; d < DS; ++d) {
            size_t ix = sb + (size_t)d * DM;
            g_sinit[ix] = s[d];
            s[d] = fmaf(g_P[ix], s[d], g_Sloc[ix]);
        }
    }
}

// ---------------------------------------------------------------------------
// Kernel 3c: seeded rescan, hybrid exp + 4-way acc tree (breaks the 16-deep
// serial FMA dependency). Writes `out` exactly once per element.
// ---------------------------------------------------------------------------
__global__ __launch_bounds__(256)
void scan_pass3(const float* __restrict__ a_log,
                const float* __restrict__ Bm,
                const float* __restrict__ Cm,
                float* __restrict__ out)
{
    int bb = blockIdx.z;
    int ch = blockIdx.y;
    int c  = blockIdx.x * 256 + threadIdx.x;

    float A2[DS], Bv[DS], Cv[DS], s[DS];
    size_t sb = (((size_t)bb * NC + ch) * DS) * DM + c;
#pragma unroll
    for (int d = 0; d < DS; ++d) {
        float z  = a_log[c * DS + d];
        float sp = fmaxf(z, 0.0f) + log1pf(__expf(-fabsf(z)));
        A2[d] = -sp * LOG2E;
        Bv[d] = Bm[c * DS + d];
        Cv[d] = Cm[c * DS + d];
        s[d]  = g_sinit[sb + (size_t)d * DM];
    }

    size_t base = ((size_t)bb * SEQ + (size_t)ch * CHUNK) * DM + c;
    const float* pdt = g_dt + base;
    const float* pxf = g_xf + base;
    float*       py  = out  + base;

    float ndt = __ldcs(pdt), nxf = __ldcs(pxf);
    for (int t = 0; t < CHUNK; ++t) {
        float dt = ndt, xf = nxf;
        if (t + 1 < CHUNK) {
            ndt = __ldcs(pdt + (size_t)(t + 1) * DM);
            nxf = __ldcs(pxf + (size_t)(t + 1) * DM);
        }
        float u = dt * xf;
        float a0 = 0.f, a1 = 0.f, a2 = 0.f, a3 = 0.f;
#pragma unroll
        for (int d = 0; d < DS; d += 4) {
            float x0 = dt * A2[d + 0], x1 = dt * A2[d + 1];
            float x2 = dt * A2[d + 2], x3 = dt * A2[d + 3];
            float e0 = (d + 0 < DS / 2) ? ex2f(x0) : ex2poly(x0);
            float e1 = (d + 1 < DS / 2) ? ex2f(x1) : ex2poly(x1);
            float e2 = (d + 2 < DS / 2) ? ex2f(x2) : ex2poly(x2);
            float e3 = (d + 3 < DS / 2) ? ex2f(x3) : ex2poly(x3);
            s[d + 0] = fmaf(e0, s[d + 0], u * Bv[d + 0]);
            s[d + 1] = fmaf(e1, s[d + 1], u * Bv[d + 1]);
            s[d + 2] = fmaf(e2, s[d + 2], u * Bv[d + 2]);
            s[d + 3] = fmaf(e3, s[d + 3], u * Bv[d + 3]);
            a0 = fmaf(s[d + 0], Cv[d + 0], a0);
            a1 = fmaf(s[d + 1], Cv[d + 1], a1);
            a2 = fmaf(s[d + 2], Cv[d + 2], a2);
            a3 = fmaf(s[d + 3], Cv[d + 3], a3);
        }
        py[(size_t)t * DM] = (a0 + a1) + (a2 + a3);
    }
}

// ---------------------------------------------------------------------------
extern "C" void kernel_launch(void* const* d_in, const int* in_sizes, int n_in,
                              void* d_out, int out_size)
{
    const float* x      = (const float*)d_in[0];  // (8,2048,1024)
    const float* a_log  = (const float*)d_in[1];  // (1024,16)
    const float* b      = (const float*)d_in[2];  // (1024,16)
    const float* c      = (const float*)d_in[3];  // (1024,16)
    const float* dt_w   = (const float*)d_in[4];  // (1024,1024)
    const float* dt_b   = (const float*)d_in[5];  // (1024,)
    const float* conv_w = (const float*)d_in[6];  // (1024,1,3)
    const float* conv_b = (const float*)d_in[7];  // (1024,)
    float* out = (float*)d_out;                   // (8,2048,1024)

    // 1a) split dt_w into bf16 hi/lo
    wsplit_kernel<<<(DM * DM / 4 + 255) / 256, 256>>>((const float4*)dt_w);

    // 1b) depthwise conv -> g_xf (fp32) + g_xh/g_xl (bf16 hi/lo)
    conv_kernel<<<(TOT / 4 + 255) / 256, 256>>>(
        (const float4*)x, (const float4*)conv_w, (const float4*)conv_b);

    // 2) dt GEMM (+sigmoid) -> g_dt
    cudaFuncSetAttribute(gemm_dt_kernel,
                         cudaFuncAttributeMaxDynamicSharedMemorySize, GEMM_SMEM);
    dim3 ggrid(DM / 128, (BSZ * SEQ) / 128);
    gemm_dt_kernel<<<ggrid, 256, GEMM_SMEM>>>(dt_b);

    // 3) chunked selective scan: reduce -> combine -> seeded rescan
    dim3 sgrid(DM / 256, NC, BSZ);              // (4, 32, 8)
    scan_pass1<<<sgrid, 256>>>(a_log, b);
    scan_pass2<<<(BSZ * DM) / 256, 256>>>();
    scan_pass3<<<sgrid, 256>>>(a_log, b, c, out);
}

// round 10
// speedup vs baseline: 1.2305x; 1.2305x over previous
#include <cuda_runtime.h>
#include <cuda_bf16.h>
#include <cstdint>

// Problem dims (fixed): B=8, N=2048, C=1024, D=16
#define BSZ 8
#define SEQ 2048
#define DM  1024
#define DS  16
#define TOT (BSZ * SEQ * DM)   // 16,777,216

#define NC    32               // scan chunks
#define CHUNK (SEQ / NC)       // 64 steps per chunk
#define DH    (DS / 2)         // states per lane (d-split)

#define LOG2E 1.4426950408889634f

// Scratch (allocation-free rule: static __device__ globals)
__device__ float          g_xf[(size_t)TOT];        // conv output fp32 (scan input)
__device__ float          g_dt[(size_t)TOT];        // dt after sigmoid scaling
__device__ __nv_bfloat16  g_xh[(size_t)TOT];        // hi(xf)
__device__ __nv_bfloat16  g_xl[(size_t)TOT];        // lo(xf)
__device__ __nv_bfloat16  g_wh[(size_t)DM * DM];    // hi(dt_w)
__device__ __nv_bfloat16  g_wl[(size_t)DM * DM];    // lo(dt_w)
__device__ float          g_A2[(size_t)DM * DS];    // -softplus(a_log)*log2e
// chunked-scan state, layout [b][ch][d][c]  (c fastest -> coalesced)
__device__ float g_P    [(size_t)BSZ * NC * DS * DM];  // chunk decay products
__device__ float g_Sloc [(size_t)BSZ * NC * DS * DM];  // chunk-local end states
__device__ float g_sinit[(size_t)BSZ * NC * DS * DM];  // per-chunk initial states

__device__ __forceinline__ float ex2f(float x) {
    float y; asm("ex2.approx.f32 %0, %1;" : "=f"(y) : "f"(x)); return y;
}
__device__ __forceinline__ float rcpf(float x) {
    float y; asm("rcp.approx.f32 %0, %1;" : "=f"(y) : "f"(x)); return y;
}
__device__ __forceinline__ void split_bf16(float v, __nv_bfloat16& h, __nv_bfloat16& l) {
    h = __float2bfloat16(v);
    l = __float2bfloat16(v - __bfloat162float(h));
}
__device__ __forceinline__ void cp16(void* s, const void* g) {
    uint32_t sa = (uint32_t)__cvta_generic_to_shared(s);
    asm volatile("cp.async.cg.shared.global [%0], [%1], 16;" :: "r"(sa), "l"(g));
}

// ---------------------------------------------------------------------------
// Kernel 0: precompute A2 table (tiny, once per launch)
// ---------------------------------------------------------------------------
__global__ void aprep_kernel(const float* __restrict__ a_log)
{
    int i = blockIdx.x * blockDim.x + threadIdx.x;
    if (i >= DM * DS) return;
    float z  = a_log[i];
    float sp = fmaxf(z, 0.0f) + log1pf(__expf(-fabsf(z)));   // softplus
    g_A2[i] = -sp * LOG2E;
}

// ---------------------------------------------------------------------------
// Kernel 1: depthwise conv k=3 pad=1 along sequence. float4-vectorized.
// ---------------------------------------------------------------------------
__global__ void conv_kernel(const float4* __restrict__ x4,
                            const float4* __restrict__ cw4,
                            const float4* __restrict__ cb4)
{
    int i4 = blockIdx.x * blockDim.x + threadIdx.x;      // 0 .. TOT/4-1
    if (i4 >= TOT / 4) return;
    int c4 = i4 & (DM / 4 - 1);
    int n  = (i4 >> 8) & (SEQ - 1);

    float4 wa = cw4[c4 * 3 + 0];
    float4 wb = cw4[c4 * 3 + 1];
    float4 wc = cw4[c4 * 3 + 2];
    float4 bb = cb4[c4];

    const float4 z = make_float4(0.f, 0.f, 0.f, 0.f);
    float4 xm = (n > 0)       ? x4[i4 - DM / 4] : z;
    float4 xc = x4[i4];
    float4 xp = (n < SEQ - 1) ? x4[i4 + DM / 4] : z;

    float4 y;
    y.x = fmaf(wa.x, xm.x, fmaf(wa.y, xc.x, fmaf(wa.z, xp.x, bb.x)));
    y.y = fmaf(wa.w, xm.y, fmaf(wb.x, xc.y, fmaf(wb.y, xp.y, bb.y)));
    y.z = fmaf(wb.z, xm.z, fmaf(wb.w, xc.z, fmaf(wc.x, xp.z, bb.z)));
    y.w = fmaf(wc.y, xm.w, fmaf(wc.z, xc.w, fmaf(wc.w, xp.w, bb.w)));

    ((float4*)g_xf)[i4] = y;

    __nv_bfloat16 h0, h1, h2, h3, l0, l1, l2, l3;
    split_bf16(y.x, h0, l0); split_bf16(y.y, h1, l1);
    split_bf16(y.z, h2, l2); split_bf16(y.w, h3, l3);
    __nv_bfloat162 hh01 = {h0, h1}, hh23 = {h2, h3};
    __nv_bfloat162 ll01 = {l0, l1}, ll23 = {l2, l3};
    uint2 hp, lp;
    hp.x = *(uint32_t*)&hh01; hp.y = *(uint32_t*)&hh23;
    lp.x = *(uint32_t*)&ll01; lp.y = *(uint32_t*)&ll23;
    *(uint2*)&g_xh[(size_t)i4 * 4] = hp;
    *(uint2*)&g_xl[(size_t)i4 * 4] = lp;
}

// ---------------------------------------------------------------------------
// Kernel 1b: split dt_w into bf16 hi/lo
// ---------------------------------------------------------------------------
__global__ void wsplit_kernel(const float4* __restrict__ w4)
{
    int i4 = blockIdx.x * blockDim.x + threadIdx.x;
    if (i4 >= DM * DM / 4) return;
    float4 v = w4[i4];
    __nv_bfloat16 h0, h1, h2, h3, l0, l1, l2, l3;
    split_bf16(v.x, h0, l0); split_bf16(v.y, h1, l1);
    split_bf16(v.z, h2, l2); split_bf16(v.w, h3, l3);
    __nv_bfloat162 hh01 = {h0, h1}, hh23 = {h2, h3};
    __nv_bfloat162 ll01 = {l0, l1}, ll23 = {l2, l3};
    uint2 hp, lp;
    hp.x = *(uint32_t*)&hh01; hp.y = *(uint32_t*)&hh23;
    lp.x = *(uint32_t*)&ll01; lp.y = *(uint32_t*)&ll23;
    *(uint2*)&g_wh[(size_t)i4 * 4] = hp;
    *(uint2*)&g_wl[(size_t)i4 * 4] = lp;
}

// ---------------------------------------------------------------------------
// Kernel 2: dt GEMM on tensor cores, bf16 3-pass hi/lo split, cp.async
// double-buffered. CTA 128x128x32, 8 warps x (32x64) via m16n8k16.
// ---------------------------------------------------------------------------
#define TBK 32
#define SPAD 40
#define PER_ARR (128 * SPAD)
#define PER_STAGE (4 * PER_ARR)
#define GEMM_SMEM (2 * PER_STAGE * 2)

__device__ __forceinline__ void mma_bf16(float* c, const uint32_t* a, const uint32_t* b) {
    asm volatile(
        "mma.sync.aligned.m16n8k16.row.col.f32.bf16.bf16.f32 "
        "{%0,%1,%2,%3},{%4,%5,%6,%7},{%8,%9},{%0,%1,%2,%3};"
        : "+f"(c[0]), "+f"(c[1]), "+f"(c[2]), "+f"(c[3])
        : "r"(a[0]), "r"(a[1]), "r"(a[2]), "r"(a[3]), "r"(b[0]), "r"(b[1]));
}

__global__ __launch_bounds__(256)
void gemm_dt_kernel(const float* __restrict__ bias)
{
    extern __shared__ __nv_bfloat16 sm[];

    const int tid  = threadIdx.x;
    const int lane = tid & 31;
    const int warp = tid >> 5;
    const int wm   = warp >> 1;
    const int wn   = warp & 1;
    const int qr   = lane >> 2;
    const int qc   = lane & 3;
    const int bm   = blockIdx.y * 128;
    const int bn   = blockIdx.x * 128;

    float acc[2][8][4];
#pragma unroll
    for (int mt = 0; mt < 2; ++mt)
#pragma unroll
        for (int nt = 0; nt < 8; ++nt)
#pragma unroll
            for (int r = 0; r < 4; ++r) acc[mt][nt][r] = 0.0f;

    auto load_stage = [&](int st, int k0) {
        __nv_bfloat16* base = sm + st * PER_STAGE;
#pragma unroll
        for (int i = 0; i < 2; ++i) {
            int f   = tid + i * 256;
            int row = f >> 2;
            int k8  = (f & 3) << 3;
            size_t ga = (size_t)(bm + row) * DM + k0 + k8;
            size_t gb = (size_t)(bn + row) * DM + k0 + k8;
            int so = row * SPAD + k8;
            cp16(base + 0 * PER_ARR + so, &g_xh[ga]);
            cp16(base + 1 * PER_ARR + so, &g_xl[ga]);
            cp16(base + 2 * PER_ARR + so, &g_wh[gb]);
            cp16(base + 3 * PER_ARR + so, &g_wl[gb]);
        }
        asm volatile("cp.async.commit_group;");
    };

    const int KT = DM / TBK;   // 32
    load_stage(0, 0);

    for (int kt = 0; kt < KT; ++kt) {
        asm volatile("cp.async.wait_group 0;");
        __syncthreads();
        if (kt + 1 < KT) load_stage((kt + 1) & 1, (kt + 1) * TBK);

        const __nv_bfloat16* Ah = sm + (kt & 1) * PER_STAGE + 0 * PER_ARR;
        const __nv_bfloat16* Al = Ah + PER_ARR;
        const __nv_bfloat16* Bh = Al + PER_ARR;
        const __nv_bfloat16* Bl = Bh + PER_ARR;

#pragma unroll
        for (int kst = 0; kst < TBK; kst += 16) {
            uint32_t ah[2][4], al[2][4];
#pragma unroll
            for (int mt = 0; mt < 2; ++mt) {
                int r0 = wm * 32 + mt * 16 + qr;
                int c0 = kst + qc * 2;
                ah[mt][0] = *(const uint32_t*)&Ah[(r0    ) * SPAD + c0    ];
                ah[mt][1] = *(const uint32_t*)&Ah[(r0 + 8) * SPAD + c0    ];
                ah[mt][2] = *(const uint32_t*)&Ah[(r0    ) * SPAD + c0 + 8];
                ah[mt][3] = *(const uint32_t*)&Ah[(r0 + 8) * SPAD + c0 + 8];
                al[mt][0] = *(const uint32_t*)&Al[(r0    ) * SPAD + c0    ];
                al[mt][1] = *(const uint32_t*)&Al[(r0 + 8) * SPAD + c0    ];
                al[mt][2] = *(const uint32_t*)&Al[(r0    ) * SPAD + c0 + 8];
                al[mt][3] = *(const uint32_t*)&Al[(r0 + 8) * SPAD + c0 + 8];
            }
            uint32_t bh[8][2], bl[8][2];
#pragma unroll
            for (int nt = 0; nt < 8; ++nt) {
                int nr = wn * 64 + nt * 8 + qr;
                int c0 = kst + qc * 2;
                bh[nt][0] = *(const uint32_t*)&Bh[nr * SPAD + c0    ];
                bh[nt][1] = *(const uint32_t*)&Bh[nr * SPAD + c0 + 8];
                bl[nt][0] = *(const uint32_t*)&Bl[nr * SPAD + c0    ];
                bl[nt][1] = *(const uint32_t*)&Bl[nr * SPAD + c0 + 8];
            }
#pragma unroll
            for (int mt = 0; mt < 2; ++mt)
#pragma unroll
                for (int nt = 0; nt < 8; ++nt) {
                    mma_bf16(acc[mt][nt], ah[mt], bh[nt]);
                    mma_bf16(acc[mt][nt], ah[mt], bl[nt]);
                    mma_bf16(acc[mt][nt], al[mt], bh[nt]);
                }
        }
        __syncthreads();
    }

#pragma unroll
    for (int mt = 0; mt < 2; ++mt) {
#pragma unroll
        for (int nt = 0; nt < 8; ++nt) {
            int row = bm + wm * 32 + mt * 16 + qr;
            int col = bn + wn * 64 + nt * 8 + qc * 2;
            float2 bb = *(const float2*)&bias[col];
#pragma unroll
            for (int half = 0; half < 2; ++half) {
                int r = row + half * 8;
                float r0 = acc[mt][nt][half * 2 + 0] + bb.x;
                float r1 = acc[mt][nt][half * 2 + 1] + bb.y;
                float s0 = rcpf(1.0f + ex2f(-r0 * LOG2E));
                float s1 = rcpf(1.0f + ex2f(-r1 * LOG2E));
                float2 v;
                v.x = fmaf(s0, 0.099f, 0.001f);
                v.y = fmaf(s1, 0.099f, 0.001f);
                *(float2*)&g_dt[(size_t)r * DM + col] = v;
            }
        }
    }
}

// ---------------------------------------------------------------------------
// Kernel 3a: chunk-local reduction, d-SPLIT: lane pairs share a channel,
// each lane owns 8 of the 16 states. No cross-lane communication.
// Block 256 threads -> 128 channels. Pure MUFU exp (poly reverted: R9 showed
// the FMA poly lengthens the critical path).
// ---------------------------------------------------------------------------
__global__ __launch_bounds__(256)
void scan_pass1(const float* __restrict__ Bm)
{
    int bb   = blockIdx.z;
    int ch   = blockIdx.y;
    int half = threadIdx.x & 1;                       // 0 or 1
    int c    = blockIdx.x * 128 + (threadIdx.x >> 1); // channel
    int d0   = half * DH;                             // first state index

    float A2[DH], Bv[DH], s[DH];
#pragma unroll
    for (int j = 0; j < DH; ++j) {
        A2[j] = g_A2[c * DS + d0 + j];
        Bv[j] = Bm  [c * DS + d0 + j];
        s[j]  = 0.0f;
    }

    size_t base = ((size_t)bb * SEQ + (size_t)ch * CHUNK) * DM + c;
    const float* pdt = g_dt + base;
    const float* pxf = g_xf + base;

    float cum = 0.0f;
    float ndt = __ldcs(pdt), nxf = __ldcs(pxf);
    for (int t = 0; t < CHUNK; ++t) {
        float dt = ndt, xf = nxf;
        if (t + 1 < CHUNK) {
            ndt = __ldcs(pdt + (size_t)(t + 1) * DM);
            nxf = __ldcs(pxf + (size_t)(t + 1) * DM);
        }
        cum += dt;
        float u = dt * xf;
#pragma unroll
        for (int j = 0; j < DH; ++j) {
            float e = ex2f(dt * A2[j]);
            s[j] = fmaf(e, s[j], u * Bv[j]);
        }
    }

    size_t sb = (((size_t)bb * NC + ch) * DS + d0) * DM + c;
#pragma unroll
    for (int j = 0; j < DH; ++j) {
        g_Sloc[sb + (size_t)j * DM] = s[j];
        g_P   [sb + (size_t)j * DM] = ex2f(A2[j] * cum);
    }
}

// ---------------------------------------------------------------------------
// Kernel 3b: combine across chunks. One thread per (b, d, c) -- each state
// scans its own chunk chain independently; fully coalesced (c fastest).
// ---------------------------------------------------------------------------
__global__ __launch_bounds__(256)
void scan_pass2()
{
    int t  = blockIdx.x * blockDim.x + threadIdx.x;   // 0 .. BSZ*DS*DM-1
    int bb = t / (DS * DM);
    int k  = t - bb * (DS * DM);                      // d*DM + c

    float s = 0.0f;
    size_t stride = (size_t)DS * DM;
    size_t ix = ((size_t)bb * NC) * stride + k;
    for (int ch = 0; ch < NC; ++ch, ix += stride) {
        g_sinit[ix] = s;
        s = fmaf(g_P[ix], s, g_Sloc[ix]);
    }
}

// ---------------------------------------------------------------------------
// Kernel 3c: seeded rescan, d-SPLIT. Lane pairs share a channel; each lane
// advances 8 states; per-step pair-sum via one shfl; even lane stores.
// ---------------------------------------------------------------------------
__global__ __launch_bounds__(256)
void scan_pass3(const float* __restrict__ Bm,
                const float* __restrict__ Cm,
                float* __restrict__ out)
{
    int bb   = blockIdx.z;
    int ch   = blockIdx.y;
    int half = threadIdx.x & 1;
    int c    = blockIdx.x * 128 + (threadIdx.x >> 1);
    int d0   = half * DH;

    float A2[DH], Bv[DH], Cv[DH], s[DH];
    size_t sb = (((size_t)bb * NC + ch) * DS + d0) * DM + c;
#pragma unroll
    for (int j = 0; j < DH; ++j) {
        A2[j] = g_A2[c * DS + d0 + j];
        Bv[j] = Bm  [c * DS + d0 + j];
        Cv[j] = Cm  [c * DS + d0 + j];
        s[j]  = g_sinit[sb + (size_t)j * DM];
    }

    size_t base = ((size_t)bb * SEQ + (size_t)ch * CHUNK) * DM + c;
    const float* pdt = g_dt + base;
    const float* pxf = g_xf + base;
    float*       py  = out  + base;

    float ndt = __ldcs(pdt), nxf = __ldcs(pxf);
    for (int t = 0; t < CHUNK; ++t) {
        float dt = ndt, xf = nxf;
        if (t + 1 < CHUNK) {
            ndt = __ldcs(pdt + (size_t)(t + 1) * DM);
            nxf = __ldcs(pxf + (size_t)(t + 1) * DM);
        }
        float u = dt * xf;
        float a0 = 0.f, a1 = 0.f;
#pragma unroll
        for (int j = 0; j < DH; j += 2) {
            float e0 = ex2f(dt * A2[j + 0]);
            float e1 = ex2f(dt * A2[j + 1]);
            s[j + 0] = fmaf(e0, s[j + 0], u * Bv[j + 0]);
            s[j + 1] = fmaf(e1, s[j + 1], u * Bv[j + 1]);
            a0 = fmaf(s[j + 0], Cv[j + 0], a0);
            a1 = fmaf(s[j + 1], Cv[j + 1], a1);
        }
        float acc = a0 + a1;
        float tot = acc + __shfl_xor_sync(0xFFFFFFFFu, acc, 1);
        if (half == 0) py[(size_t)t * DM] = tot;
    }
}

// ---------------------------------------------------------------------------
extern "C" void kernel_launch(void* const* d_in, const int* in_sizes, int n_in,
                              void* d_out, int out_size)
{
    const float* x      = (const float*)d_in[0];  // (8,2048,1024)
    const float* a_log  = (const float*)d_in[1];  // (1024,16)
    const float* b      = (const float*)d_in[2];  // (1024,16)
    const float* c      = (const float*)d_in[3];  // (1024,16)
    const float* dt_w   = (const float*)d_in[4];  // (1024,1024)
    const float* dt_b   = (const float*)d_in[5];  // (1024,)
    const float* conv_w = (const float*)d_in[6];  // (1024,1,3)
    const float* conv_b = (const float*)d_in[7];  // (1024,)
    float* out = (float*)d_out;                   // (8,2048,1024)

    // 0) A2 table + dt_w split (tiny)
    aprep_kernel<<<(DM * DS + 255) / 256, 256>>>(a_log);
    wsplit_kernel<<<(DM * DM / 4 + 255) / 256, 256>>>((const float4*)dt_w);

    // 1) depthwise conv -> g_xf (fp32) + g_xh/g_xl (bf16 hi/lo)
    conv_kernel<<<(TOT / 4 + 255) / 256, 256>>>(
        (const float4*)x, (const float4*)conv_w, (const float4*)conv_b);

    // 2) dt GEMM (+sigmoid) -> g_dt
    cudaFuncSetAttribute(gemm_dt_kernel,
                         cudaFuncAttributeMaxDynamicSharedMemorySize, GEMM_SMEM);
    dim3 ggrid(DM / 128, (BSZ * SEQ) / 128);
    gemm_dt_kernel<<<ggrid, 256, GEMM_SMEM>>>(dt_b);

    // 3) chunked selective scan: reduce -> combine -> seeded rescan
    dim3 sgrid(DM / 128, NC, BSZ);              // (8, 32, 8) = 2048 blocks
    scan_pass1<<<sgrid, 256>>>(b);
    scan_pass2<<<(BSZ * DS * DM) / 256, 256>>>();
    scan_pass3<<<sgrid, 256>>>(b, c, out);
}

// round 12
// speedup vs baseline: 1.2744x; 1.0357x over previous
#include <cuda_runtime.h>
#include <cuda_bf16.h>
#include <cstdint>

// Problem dims (fixed): B=8, N=2048, C=1024, D=16
#define BSZ 8
#define SEQ 2048
#define DM  1024
#define DS  16
#define TOT (BSZ * SEQ * DM)   // 16,777,216

#define NC    32               // scan chunks
#define CHUNK (SEQ / NC)       // 64 steps per chunk
#define DH    (DS / 2)         // states per lane (d-split)

#define LOG2E 1.4426950408889634f

// Scratch (allocation-free rule: static __device__ globals)
__device__ float          g_xf[(size_t)TOT];        // conv output fp32 (scan input)
__device__ float          g_dt[(size_t)TOT];        // dt after sigmoid scaling
__device__ __nv_bfloat16  g_xh[(size_t)TOT];        // hi(xf)
__device__ __nv_bfloat16  g_xl[(size_t)TOT];        // lo(xf)
__device__ __nv_bfloat16  g_wh[(size_t)DM * DM];    // hi(dt_w)
__device__ __nv_bfloat16  g_wl[(size_t)DM * DM];    // lo(dt_w)
__device__ float          g_A2[(size_t)DM * DS];    // -softplus(a_log)*log2e
// chunked-scan state, layout [b][ch][d][c]  (c fastest -> coalesced)
__device__ float g_P    [(size_t)BSZ * NC * DS * DM];  // chunk decay products
__device__ float g_Sloc [(size_t)BSZ * NC * DS * DM];  // chunk-local end states
__device__ float g_sinit[(size_t)BSZ * NC * DS * DM];  // per-chunk initial states

__device__ __forceinline__ float ex2f(float x) {
    float y; asm("ex2.approx.f32 %0, %1;" : "=f"(y) : "f"(x)); return y;
}
__device__ __forceinline__ float rcpf(float x) {
    float y; asm("rcp.approx.f32 %0, %1;" : "=f"(y) : "f"(x)); return y;
}
__device__ __forceinline__ void split_bf16(float v, __nv_bfloat16& h, __nv_bfloat16& l) {
    h = __float2bfloat16(v);
    l = __float2bfloat16(v - __bfloat162float(h));
}
__device__ __forceinline__ void cp16s(uint32_t s, const void* g) {
    asm volatile("cp.async.cg.shared.global [%0], [%1], 16;" :: "r"(s), "l"(g));
}
__device__ __forceinline__ uint32_t smem_u32(const void* p) {
    uint32_t a;
    asm("{ .reg .u64 t; cvta.to.shared.u64 t, %1; cvt.u32.u64 %0, t; }" : "=r"(a) : "l"(p));
    return a;
}
#define LDSM4(r0, r1, r2, r3, addr) \
    asm volatile("ldmatrix.sync.aligned.m8n8.x4.shared.b16 {%0,%1,%2,%3}, [%4];" \
                 : "=r"(r0), "=r"(r1), "=r"(r2), "=r"(r3) : "r"(addr))

// ---------------------------------------------------------------------------
// Kernel 0: precompute A2 table (tiny, once per launch)
// ---------------------------------------------------------------------------
__global__ void aprep_kernel(const float* __restrict__ a_log)
{
    int i = blockIdx.x * blockDim.x + threadIdx.x;
    if (i >= DM * DS) return;
    float z  = a_log[i];
    float sp = fmaxf(z, 0.0f) + log1pf(__expf(-fabsf(z)));   // softplus
    g_A2[i] = -sp * LOG2E;
}

// ---------------------------------------------------------------------------
// Kernel 1: depthwise conv k=3 pad=1 along sequence. float4-vectorized.
// ---------------------------------------------------------------------------
__global__ void conv_kernel(const float4* __restrict__ x4,
                            const float4* __restrict__ cw4,
                            const float4* __restrict__ cb4)
{
    int i4 = blockIdx.x * blockDim.x + threadIdx.x;      // 0 .. TOT/4-1
    if (i4 >= TOT / 4) return;
    int c4 = i4 & (DM / 4 - 1);
    int n  = (i4 >> 8) & (SEQ - 1);

    float4 wa = cw4[c4 * 3 + 0];
    float4 wb = cw4[c4 * 3 + 1];
    float4 wc = cw4[c4 * 3 + 2];
    float4 bb = cb4[c4];

    const float4 z = make_float4(0.f, 0.f, 0.f, 0.f);
    float4 xm = (n > 0)       ? x4[i4 - DM / 4] : z;
    float4 xc = x4[i4];
    float4 xp = (n < SEQ - 1) ? x4[i4 + DM / 4] : z;

    float4 y;
    y.x = fmaf(wa.x, xm.x, fmaf(wa.y, xc.x, fmaf(wa.z, xp.x, bb.x)));
    y.y = fmaf(wa.w, xm.y, fmaf(wb.x, xc.y, fmaf(wb.y, xp.y, bb.y)));
    y.z = fmaf(wb.z, xm.z, fmaf(wb.w, xc.z, fmaf(wc.x, xp.z, bb.z)));
    y.w = fmaf(wc.y, xm.w, fmaf(wc.z, xc.w, fmaf(wc.w, xp.w, bb.w)));

    ((float4*)g_xf)[i4] = y;

    __nv_bfloat16 h0, h1, h2, h3, l0, l1, l2, l3;
    split_bf16(y.x, h0, l0); split_bf16(y.y, h1, l1);
    split_bf16(y.z, h2, l2); split_bf16(y.w, h3, l3);
    __nv_bfloat162 hh01 = {h0, h1}, hh23 = {h2, h3};
    __nv_bfloat162 ll01 = {l0, l1}, ll23 = {l2, l3};
    uint2 hp, lp;
    hp.x = *(uint32_t*)&hh01; hp.y = *(uint32_t*)&hh23;
    lp.x = *(uint32_t*)&ll01; lp.y = *(uint32_t*)&ll23;
    *(uint2*)&g_xh[(size_t)i4 * 4] = hp;
    *(uint2*)&g_xl[(size_t)i4 * 4] = lp;
}

// ---------------------------------------------------------------------------
// Kernel 1b: split dt_w into bf16 hi/lo
// ---------------------------------------------------------------------------
__global__ void wsplit_kernel(const float4* __restrict__ w4)
{
    int i4 = blockIdx.x * blockDim.x + threadIdx.x;
    if (i4 >= DM * DM / 4) return;
    float4 v = w4[i4];
    __nv_bfloat16 h0, h1, h2, h3, l0, l1, l2, l3;
    split_bf16(v.x, h0, l0); split_bf16(v.y, h1, l1);
    split_bf16(v.z, h2, l2); split_bf16(v.w, h3, l3);
    __nv_bfloat162 hh01 = {h0, h1}, hh23 = {h2, h3};
    __nv_bfloat162 ll01 = {l0, l1}, ll23 = {l2, l3};
    uint2 hp, lp;
    hp.x = *(uint32_t*)&hh01; hp.y = *(uint32_t*)&hh23;
    lp.x = *(uint32_t*)&ll01; lp.y = *(uint32_t*)&ll23;
    *(uint2*)&g_wh[(size_t)i4 * 4] = hp;
    *(uint2*)&g_wl[(size_t)i4 * 4] = lp;
}

// ---------------------------------------------------------------------------
// Kernel 2: dt GEMM on tensor cores (mma.sync; tcgen05 unavailable in this
// toolchain -- compute_103 virtual target rejects 'a'-suffix features).
// bf16 3-pass hi/lo split, cp.async double-buffered, CTA 128x128x32,
// 8 warps x (32x64). Fragment loads via ldmatrix.x4 (48 LDS -> 12 LDSM).
// ---------------------------------------------------------------------------
#define TBK 32
#define SPAD 40
#define PER_ARR (128 * SPAD)           // elements
#define ARRB (PER_ARR * 2)             // bytes per array (10240)
#define PER_STAGE (4 * PER_ARR)
#define STGB (PER_STAGE * 2)           // bytes per stage (40960)
#define GEMM_SMEM (2 * STGB)

__device__ __forceinline__ void mma_bf16(float* c, const uint32_t* a, const uint32_t* b) {
    asm volatile(
        "mma.sync.aligned.m16n8k16.row.col.f32.bf16.bf16.f32 "
        "{%0,%1,%2,%3},{%4,%5,%6,%7},{%8,%9},{%0,%1,%2,%3};"
        : "+f"(c[0]), "+f"(c[1]), "+f"(c[2]), "+f"(c[3])
        : "r"(a[0]), "r"(a[1]), "r"(a[2]), "r"(a[3]), "r"(b[0]), "r"(b[1]));
}

__global__ __launch_bounds__(256)
void gemm_dt_kernel(const float* __restrict__ bias)
{
    extern __shared__ __nv_bfloat16 sm[];
    const uint32_t smb = smem_u32(sm);

    const int tid  = threadIdx.x;
    const int lane = tid & 31;
    const int warp = tid >> 5;
    const int wm   = warp >> 1;          // 0..3 -> 32-row slices
    const int wn   = warp & 1;           // 0..1 -> 64-col slices
    const int qr   = lane >> 2;
    const int qc   = lane & 3;
    const int bm   = blockIdx.y * 128;
    const int bn   = blockIdx.x * 128;

    // ldmatrix per-lane fragment addressing
    const int lr  = lane & 7;            // row within 8x8 tile
    const int g01 = (lane >> 3) & 1;     // tile-pair selector (low)
    const int g23 = lane >> 4;           // tile-pair selector (high)
    // A fragment (16x16): tiles (r0,k0)(r+8,k0)(r0,k8)(r+8,k8)
    const int aRow    = wm * 32 + g01 * 8 + lr;
    const int aColOff = g23 * 8;
    // B fragments (pairs of 8x16): tiles (n0,k0)(n0,k8)(n0+8,k0)(n0+8,k8)
    const int bRow    = wn * 64 + g23 * 8 + lr;
    const int bColOff = g01 * 8;

    float acc[2][8][4];
#pragma unroll
    for (int mt = 0; mt < 2; ++mt)
#pragma unroll
        for (int nt = 0; nt < 8; ++nt)
#pragma unroll
            for (int r = 0; r < 4; ++r) acc[mt][nt][r] = 0.0f;

    auto load_stage = [&](int st, int k0) {
        uint32_t base = smb + (uint32_t)st * STGB;
#pragma unroll
        for (int i = 0; i < 2; ++i) {
            int f   = tid + i * 256;
            int row = f >> 2;
            int k8  = (f & 3) << 3;
            size_t ga = (size_t)(bm + row) * DM + k0 + k8;
            size_t gb = (size_t)(bn + row) * DM + k0 + k8;
            uint32_t so = (uint32_t)(row * SPAD + k8) * 2;
            cp16s(base + 0 * ARRB + so, &g_xh[ga]);
            cp16s(base + 1 * ARRB + so, &g_xl[ga]);
            cp16s(base + 2 * ARRB + so, &g_wh[gb]);
            cp16s(base + 3 * ARRB + so, &g_wl[gb]);
        }
        asm volatile("cp.async.commit_group;");
    };

    const int KT = DM / TBK;   // 32
    load_stage(0, 0);

    for (int kt = 0; kt < KT; ++kt) {
        asm volatile("cp.async.wait_group 0;");
        __syncthreads();
        if (kt + 1 < KT) load_stage((kt + 1) & 1, (kt + 1) * TBK);

        uint32_t stage = smb + (uint32_t)(kt & 1) * STGB;
        uint32_t aBase = stage + (uint32_t)(aRow * SPAD + aColOff) * 2;
        uint32_t bBase = stage + 2 * ARRB + (uint32_t)(bRow * SPAD + bColOff) * 2;

#pragma unroll
        for (int kst = 0; kst < TBK; kst += 16) {
            uint32_t kb = (uint32_t)(kst * 2);
            uint32_t ah[2][4], al[2][4], bh[8][2], bl[8][2];
#pragma unroll
            for (int mt = 0; mt < 2; ++mt) {
                uint32_t aoff = aBase + (uint32_t)(mt * 16 * SPAD) * 2 + kb;
                LDSM4(ah[mt][0], ah[mt][1], ah[mt][2], ah[mt][3], aoff);
                LDSM4(al[mt][0], al[mt][1], al[mt][2], al[mt][3], aoff + ARRB);
            }
#pragma unroll
            for (int p = 0; p < 4; ++p) {
                uint32_t boff = bBase + (uint32_t)(p * 16 * SPAD) * 2 + kb;
                LDSM4(bh[2 * p][0], bh[2 * p][1], bh[2 * p + 1][0], bh[2 * p + 1][1], boff);
                LDSM4(bl[2 * p][0], bl[2 * p][1], bl[2 * p + 1][0], bl[2 * p + 1][1], boff + ARRB);
            }
#pragma unroll
            for (int mt = 0; mt < 2; ++mt)
#pragma unroll
                for (int nt = 0; nt < 8; ++nt) {
                    mma_bf16(acc[mt][nt], ah[mt], bh[nt]);   // hi*hi
                    mma_bf16(acc[mt][nt], ah[mt], bl[nt]);   // hi*lo
                    mma_bf16(acc[mt][nt], al[mt], bh[nt]);   // lo*hi
                }
        }
        __syncthreads();
    }

    // epilogue: bias + sigmoid scaling
#pragma unroll
    for (int mt = 0; mt < 2; ++mt) {
#pragma unroll
        for (int nt = 0; nt < 8; ++nt) {
            int row = bm + wm * 32 + mt * 16 + qr;
            int col = bn + wn * 64 + nt * 8 + qc * 2;
            float2 bb = *(const float2*)&bias[col];
#pragma unroll
            for (int half = 0; half < 2; ++half) {
                int r = row + half * 8;
                float r0 = acc[mt][nt][half * 2 + 0] + bb.x;
                float r1 = acc[mt][nt][half * 2 + 1] + bb.y;
                float s0 = rcpf(1.0f + ex2f(-r0 * LOG2E));
                float s1 = rcpf(1.0f + ex2f(-r1 * LOG2E));
                float2 v;
                v.x = fmaf(s0, 0.099f, 0.001f);
                v.y = fmaf(s1, 0.099f, 0.001f);
                *(float2*)&g_dt[(size_t)r * DM + col] = v;
            }
        }
    }
}

// ---------------------------------------------------------------------------
// Kernel 3a: chunk-local reduction, d-SPLIT (R10 winner, unchanged).
// ---------------------------------------------------------------------------
__global__ __launch_bounds__(256)
void scan_pass1(const float* __restrict__ Bm)
{
    int bb   = blockIdx.z;
    int ch   = blockIdx.y;
    int half = threadIdx.x & 1;
    int c    = blockIdx.x * 128 + (threadIdx.x >> 1);
    int d0   = half * DH;

    float A2[DH], Bv[DH], s[DH];
#pragma unroll
    for (int j = 0; j < DH; ++j) {
        A2[j] = g_A2[c * DS + d0 + j];
        Bv[j] = Bm  [c * DS + d0 + j];
        s[j]  = 0.0f;
    }

    size_t base = ((size_t)bb * SEQ + (size_t)ch * CHUNK) * DM + c;
    const float* pdt = g_dt + base;
    const float* pxf = g_xf + base;

    float cum = 0.0f;
    float ndt = __ldcs(pdt), nxf = __ldcs(pxf);
    for (int t = 0; t < CHUNK; ++t) {
        float dt = ndt, xf = nxf;
        if (t + 1 < CHUNK) {
            ndt = __ldcs(pdt + (size_t)(t + 1) * DM);
            nxf = __ldcs(pxf + (size_t)(t + 1) * DM);
        }
        cum += dt;
        float u = dt * xf;
#pragma unroll
        for (int j = 0; j < DH; ++j) {
            float e = ex2f(dt * A2[j]);
            s[j] = fmaf(e, s[j], u * Bv[j]);
        }
    }

    size_t sb = (((size_t)bb * NC + ch) * DS + d0) * DM + c;
#pragma unroll
    for (int j = 0; j < DH; ++j) {
        g_Sloc[sb + (size_t)j * DM] = s[j];
        g_P   [sb + (size_t)j * DM] = ex2f(A2[j] * cum);
    }
}

// ---------------------------------------------------------------------------
// Kernel 3b: combine across chunks. One thread per (b, d, c).
// ---------------------------------------------------------------------------
__global__ __launch_bounds__(256)
void scan_pass2()
{
    int t  = blockIdx.x * blockDim.x + threadIdx.x;
    int bb = t / (DS * DM);
    int k  = t - bb * (DS * DM);

    float s = 0.0f;
    size_t stride = (size_t)DS * DM;
    size_t ix = ((size_t)bb * NC) * stride + k;
    for (int ch = 0; ch < NC; ++ch, ix += stride) {
        g_sinit[ix] = s;
        s = fmaf(g_P[ix], s, g_Sloc[ix]);
    }
}

// ---------------------------------------------------------------------------
// Kernel 3c: seeded rescan, d-SPLIT + pair shfl (R10 winner, unchanged).
// ---------------------------------------------------------------------------
__global__ __launch_bounds__(256)
void scan_pass3(const float* __restrict__ Bm,
                const float* __restrict__ Cm,
                float* __restrict__ out)
{
    int bb   = blockIdx.z;
    int ch   = blockIdx.y;
    int half = threadIdx.x & 1;
    int c    = blockIdx.x * 128 + (threadIdx.x >> 1);
    int d0   = half * DH;

    float A2[DH], Bv[DH], Cv[DH], s[DH];
    size_t sb = (((size_t)bb * NC + ch) * DS + d0) * DM + c;
#pragma unroll
    for (int j = 0; j < DH; ++j) {
        A2[j] = g_A2[c * DS + d0 + j];
        Bv[j] = Bm  [c * DS + d0 + j];
        Cv[j] = Cm  [c * DS + d0 + j];
        s[j]  = g_sinit[sb + (size_t)j * DM];
    }

    size_t base = ((size_t)bb * SEQ + (size_t)ch * CHUNK) * DM + c;
    const float* pdt = g_dt + base;
    const float* pxf = g_xf + base;
    float*       py  = out  + base;

    float ndt = __ldcs(pdt), nxf = __ldcs(pxf);
    for (int t = 0; t < CHUNK; ++t) {
        float dt = ndt, xf = nxf;
        if (t + 1 < CHUNK) {
            ndt = __ldcs(pdt + (size_t)(t + 1) * DM);
            nxf = __ldcs(pxf + (size_t)(t + 1) * DM);
        }
        float u = dt * xf;
        float a0 = 0.f, a1 = 0.f;
#pragma unroll
        for (int j = 0; j < DH; j += 2) {
            float e0 = ex2f(dt * A2[j + 0]);
            float e1 = ex2f(dt * A2[j + 1]);
            s[j + 0] = fmaf(e0, s[j + 0], u * Bv[j + 0]);
            s[j + 1] = fmaf(e1, s[j + 1], u * Bv[j + 1]);
            a0 = fmaf(s[j + 0], Cv[j + 0], a0);
            a1 = fmaf(s[j + 1], Cv[j + 1], a1);
        }
        float acc = a0 + a1;
        float tot = acc + __shfl_xor_sync(0xFFFFFFFFu, acc, 1);
        if (half == 0) py[(size_t)t * DM] = tot;
    }
}

// ---------------------------------------------------------------------------
extern "C" void kernel_launch(void* const* d_in, const int* in_sizes, int n_in,
                              void* d_out, int out_size)
{
    const float* x      = (const float*)d_in[0];  // (8,2048,1024)
    const float* a_log  = (const float*)d_in[1];  // (1024,16)
    const float* b      = (const float*)d_in[2];  // (1024,16)
    const float* c      = (const float*)d_in[3];  // (1024,16)
    const float* dt_w   = (const float*)d_in[4];  // (1024,1024)
    const float* dt_b   = (const float*)d_in[5];  // (1024,)
    const float* conv_w = (const float*)d_in[6];  // (1024,1,3)
    const float* conv_b = (const float*)d_in[7];  // (1024,)
    float* out = (float*)d_out;                   // (8,2048,1024)

    // 0) A2 table + dt_w split (tiny)
    aprep_kernel<<<(DM * DS + 255) / 256, 256>>>(a_log);
    wsplit_kernel<<<(DM * DM / 4 + 255) / 256, 256>>>((const float4*)dt_w);

    // 1) depthwise conv -> g_xf (fp32) + g_xh/g_xl (bf16 hi/lo)
    conv_kernel<<<(TOT / 4 + 255) / 256, 256>>>(
        (const float4*)x, (const float4*)conv_w, (const float4*)conv_b);

    // 2) dt GEMM (+sigmoid) -> g_dt
    cudaFuncSetAttribute(gemm_dt_kernel,
                         cudaFuncAttributeMaxDynamicSharedMemorySize, GEMM_SMEM);
    dim3 ggrid(DM / 128, (BSZ * SEQ) / 128);      // (8, 128)
    gemm_dt_kernel<<<ggrid, 256, GEMM_SMEM>>>(dt_b);

    // 3) chunked selective scan: reduce -> combine -> seeded rescan
    dim3 sgrid(DM / 128, NC, BSZ);                // (8, 32, 8)
    scan_pass1<<<sgrid, 256>>>(b);
    scan_pass2<<<(BSZ * DS * DM) / 256, 256>>>();
    scan_pass3<<<sgrid, 256>>>(b, c, out);
}